// round 4
// baseline (speedup 1.0000x reference)
#include <cuda_runtime.h>
#include <cstdint>

// CostVolumeLayer3D, B=2 C=64 D=32 H=64 W=64, R=2.
// out[b, ch(s,dsh), d, h, w] = (1/125) * sum_c x1[b,c,d,h,w] * x2[b,c,d-dsh,h-i_s,w-j_s]
//   s in [-4,4], dsh in [-2,2], (i_s,j_s) = (min(2,s+2), max(-2,s-2)),
//   ch = (5s+dsh) mod 125. Channels 23..102 are identically zero.
// Thread = (w-pair) x (d-pair): 4 voxels, 90 f32x2 accumulators.
// 128-thread CTA, 2 CTAs/SM, 6-buffer cp.async pipeline, 1 barrier per 2 channels,
// x1 streamed via register LDG prefetch (never touches smem).

#define LD64(p) (*reinterpret_cast<const unsigned long long*>(p))

static __device__ __forceinline__ void cp16(uint32_t dst, const float* src, int vsz) {
    asm volatile("cp.async.cg.shared.global [%0], [%1], 16, %2;"
                 :: "r"(dst), "l"(src), "r"(vsz));
}
static __device__ __forceinline__ unsigned long long pk2(uint32_t lo, uint32_t hi) {
    unsigned long long r;
    asm("mov.b64 %0, {%1,%2};" : "=l"(r) : "r"(lo), "r"(hi));
    return r;
}
static __device__ __forceinline__ void unpk(uint32_t& lo, uint32_t& hi, unsigned long long v) {
    asm("mov.b64 {%0,%1}, %2;" : "=r"(lo), "=r"(hi) : "l"(v));
}
static __device__ __forceinline__ void fma2(unsigned long long& acc,
                                            unsigned long long a, unsigned long long b) {
    asm("fma.rn.f32x2 %0, %1, %2, %0;" : "+l"(acc) : "l"(a), "l"(b));
}
static __device__ __forceinline__ unsigned long long mul2(unsigned long long a,
                                                          unsigned long long b) {
    unsigned long long r;
    asm("mul.rn.f32x2 %0, %1, %2;" : "=l"(r) : "l"(a), "l"(b));
    return r;
}

// Per-buffer smem (floats): x2 only, 6 planes * (8 rows * 72 cols) = 3456 floats
// (13824 B). smem col = global_w + 4; W halo at cols 2,3,68,69. 6 buffers.
extern __shared__ float sm[];

__global__ void __launch_bounds__(128, 2)
cv3d_kernel(const float* __restrict__ x1, const float* __restrict__ x2,
            float* __restrict__ out)
{
    const int tid = threadIdx.x;
    const int hl  = tid >> 5;           // 0..3: h row within tile (warp = one row)
    const int w   = (tid & 31) * 2;     // even w; thread owns (w, w+1)
    const int h0  = blockIdx.x * 4;
    const int d0  = blockIdx.y * 2;
    const int b   = blockIdx.z;

    const float* x1b = x1 + (size_t)b * 8388608;
    const float* x2b = x2 + (size_t)b * 8388608;
    const uint32_t smb = (uint32_t)__cvta_generic_to_shared(sm);

    // ---- cp.async chunk geometry: chunk q = tid + 128k  =>  plane = k,
    //      row = tid>>4 (8 rows), cw = tid&15 (16 x 16B). Compact tables.
    const int crow = tid >> 4, ccw = tid & 15;
    const int gh   = h0 - 2 + crow;
    const bool ghok = ((unsigned)gh < 64u);
    const float* srow = x2b + (size_t)(ghok ? gh : 0) * 64 + ccw * 4;
    const uint32_t cdst0 = smb + (uint32_t)(crow * 72 + 4 + ccw * 4) * 4u;
    int vm = 0;
    #pragma unroll
    for (int k = 0; k < 6; ++k) {
        int gd = d0 - 2 + k;
        if (ghok && (unsigned)gd < 32u) vm |= (1 << k);
    }

    // ---- prologue: prefetch channel pairs 0 (bufs 0,1) and 1 (bufs 2,3) ----
    #pragma unroll
    for (int pr = 0; pr < 2; ++pr) {
        #pragma unroll
        for (int k = 0; k < 6; ++k) {
            int gd = d0 - 2 + k;
            int gdc = gd < 0 ? 0 : (gd > 31 ? 31 : gd);
            int vz = ((vm >> k) & 1) * 16;
            const float* s = srow + (size_t)gdc * 4096 + (size_t)(2 * pr) * 131072;
            uint32_t dd = cdst0 + (uint32_t)k * 2304u + (uint32_t)(2 * pr) * 13824u;
            cp16(dd, s, vz);
            cp16(dd + 13824u, s + 131072, vz);
        }
        asm volatile("cp.async.commit_group;");
    }

    // ---- x1: register-resident, prefetched one channel-pair ahead ----
    const float* px1 = x1b + (size_t)d0 * 4096 + (size_t)(h0 + hl) * 64 + w;
    unsigned long long A0a = LD64(px1);
    unsigned long long A1a = LD64(px1 + 4096);
    unsigned long long A0b = LD64(px1 + 131072);
    unsigned long long A1b = LD64(px1 + 131072 + 4096);

    // ---- zero W-halo columns of all 6 buffers (image edge => always 0) ----
    for (int q = tid; q < 288; q += 128) {
        int buf = q / 48, r = q % 48, pl = r >> 3, row = r & 7;
        float* hp = sm + buf * 3456 + pl * 576 + row * 72;
        hp[2] = 0.f; hp[3] = 0.f; hp[68] = 0.f; hp[69] = 0.f;
    }

    // ---- zero the 80 never-written output channels (23..102) for this tile ----
    {
        float* zb = out + (size_t)b * 16384000 + (size_t)23 * 131072
                        + (size_t)d0 * 4096 + (size_t)h0 * 64;
        int dd = (tid >> 6) & 1, row = (tid >> 4) & 3, cw = tid & 15;
        float* base = zb + dd * 4096 + row * 64 + cw * 4;
        const float4 z = make_float4(0.f, 0.f, 0.f, 0.f);
        #pragma unroll 4
        for (int ch = 0; ch < 80; ++ch)
            *reinterpret_cast<float4*>(base + (size_t)ch * 131072) = z;
    }

    // ---- accumulators: [d-index][dsh+2][s+4], f32x2 lanes = (w, w+1) ----
    unsigned long long acc[2][5][9];
    #pragma unroll
    for (int a = 0; a < 2; ++a)
        #pragma unroll
        for (int u = 0; u < 5; ++u)
            #pragma unroll
            for (int v = 0; v < 9; ++v) acc[a][u][v] = 0ull;

    int cb = 0;     // buffer of first channel of current pair
    int pb = 4;     // buffer of first channel of the pair to prefetch (i+2)

    #pragma unroll 1
    for (int i = 0; i < 32; ++i) {
        if (i < 31) asm volatile("cp.async.wait_group 1;");
        else        asm volatile("cp.async.wait_group 0;");
        __syncthreads();

        // x1 prefetch for next pair (DRAM-latency tolerant: consumed next iter)
        unsigned long long N0a = 0, N1a = 0, N0b = 0, N1b = 0;
        if (i < 31) {
            const float* nx = px1 + (size_t)(2 * i + 2) * 131072;
            N0a = LD64(nx);          N1a = LD64(nx + 4096);
            N0b = LD64(nx + 131072); N1b = LD64(nx + 131072 + 4096);
        }

        // x2 prefetch for pair i+2
        if (i < 30) {
            const uint32_t pbo = (uint32_t)pb * 13824u;
            const float* sc = srow + (size_t)(2 * i + 4) * 131072;
            #pragma unroll
            for (int k = 0; k < 6; ++k) {
                int gd = d0 - 2 + k;
                int gdc = gd < 0 ? 0 : (gd > 31 ? 31 : gd);
                int vz = ((vm >> k) & 1) * 16;
                const float* s = sc + (size_t)gdc * 4096;
                uint32_t dd = cdst0 + (uint32_t)k * 2304u + pbo;
                cp16(dd, s, vz);
                cp16(dd + 13824u, s + 131072, vz);
            }
            asm volatile("cp.async.commit_group;");
        }

        // compute both channels of the pair
        #pragma unroll
        for (int j = 0; j < 2; ++j) {
            const unsigned long long A0 = j ? A0b : A0a;
            const unsigned long long A1 = j ? A1b : A1a;
            const float* xw = sm + (cb + j) * 3456 + hl * 72 + (w + 4);

            #pragma unroll
            for (int p = 0; p < 6; ++p) {               // x2 plane gd = d0-2+p
                const float* pp = xw + p * 576;
                unsigned long long f0 = LD64(pp - 2);   // row gh-2: ww-2,ww-1
                unsigned long long f2 = LD64(pp);       //           ww,  ww+1
                unsigned long long f4 = LD64(pp + 2);   //           ww+2,ww+3
                unsigned long long l1 = LD64(pp + 74);  // row gh-1: ww+2,ww+3
                unsigned long long l2 = LD64(pp + 146); // row gh
                unsigned long long l3 = LD64(pp + 218); // row gh+1
                unsigned long long l4 = LD64(pp + 290); // row gh+2
                uint32_t f0lo, f0hi, f2lo, f2hi, f4lo, f4hi;
                unpk(f0lo, f0hi, f0); unpk(f2lo, f2hi, f2); unpk(f4lo, f4hi, f4);
                unsigned long long bb[9];
                bb[0] = l4;                 // s=-4
                bb[1] = l3;                 // s=-3
                bb[2] = l2;                 // s=-2
                bb[3] = l1;                 // s=-1
                bb[4] = f4;                 // s= 0
                bb[5] = pk2(f2hi, f4lo);    // s= 1
                bb[6] = f2;                 // s= 2
                bb[7] = pk2(f0hi, f2lo);    // s= 3
                bb[8] = f0;                 // s= 4
                if (p <= 4) {               // voxel d0:   u = 4-p
                    #pragma unroll
                    for (int v = 0; v < 9; ++v) fma2(acc[0][4 - p][v], A0, bb[v]);
                }
                if (p >= 1) {               // voxel d0+1: u = 5-p
                    #pragma unroll
                    for (int v = 0; v < 9; ++v) fma2(acc[1][5 - p][v], A1, bb[v]);
                }
            }
        }

        A0a = N0a; A1a = N1a; A0b = N0b; A1b = N1b;
        cb += 2; if (cb >= 6) cb = 0;
        pb += 2; if (pb >= 6) pb = 0;
    }

    // ---- epilogue: scale by 1/125 and store ----
    const uint32_t invb = __float_as_uint(1.0f / 125.0f);
    const unsigned long long invv = pk2(invb, invb);
    float* ob = out + (size_t)b * 16384000 + (size_t)d0 * 4096
                    + (size_t)(h0 + hl) * 64 + w;
    #pragma unroll
    for (int a = 0; a < 2; ++a)
        #pragma unroll
        for (int u = 0; u < 5; ++u)
            #pragma unroll
            for (int v = 0; v < 9; ++v) {
                int ch = (5 * (v - 4) + (u - 2)) % 125;
                if (ch < 0) ch += 125;
                unsigned long long r = mul2(acc[a][u][v], invv);
                *reinterpret_cast<unsigned long long*>(
                    ob + (size_t)ch * 131072 + a * 4096) = r;
            }
}

extern "C" void kernel_launch(void* const* d_in, const int* in_sizes, int n_in,
                              void* d_out, int out_size) {
    const float* x1 = (const float*)d_in[0];
    const float* x2 = (const float*)d_in[1];
    float* out = (float*)d_out;
    cudaFuncSetAttribute(cv3d_kernel,
                         cudaFuncAttributeMaxDynamicSharedMemorySize, 82944);
    cv3d_kernel<<<dim3(16, 16, 2), 128, 82944>>>(x1, x2, out);
}